// round 2
// baseline (speedup 1.0000x reference)
#include <cuda_runtime.h>
#include <cstdint>
#include <cstddef>

// DecoderCBatchNorm fused kernel.
//   B=16, T=4096, L=4, H=W=128, D=32.
// Phase A: warp-cooperative bilinear gather (lane = channel, coalesced line loads).
// Phase B: thread-per-point MLP with SMEM-resident weights and packed f32x2 FMAs.

#define THREADS 256
#define TILE    256
#define NBLK    256        // 65536 points / 256
#define NVIEW   4
#define HW      128
#define DD      32

// shared-memory float offsets
#define OFF_W0   0          // 5 x 32 x 32
#define OFF_W1   5120
#define OFF_B0   10240      // 5 x 32
#define OFF_B1   10400
#define OFF_WP   10560      // 3 x 32
#define OFF_BP   10656      // 32
#define OFF_WO   10688      // 32
#define OFF_BO   10720      // 1 (+pad)
#define OFF_C    10724      // 4 x 12  (C_mat for this batch)
#define OFF_P    10772      // 256 x 3
#define OFF_CF   11540      // 256 x 33 (padded, conflict-free)
#define SMEM_FLOATS 19988
#define SMEM_BYTES  (SMEM_FLOATS * 4)

static __device__ __forceinline__ unsigned long long pack2(float a, float b) {
    unsigned long long r;
    asm("mov.b64 %0, {%1, %2};" : "=l"(r) : "f"(a), "f"(b));
    return r;
}
static __device__ __forceinline__ void unpack2(unsigned long long v, float& a, float& b) {
    asm("mov.b64 {%0, %1}, %2;" : "=f"(a), "=f"(b) : "l"(v));
}
static __device__ __forceinline__ void fma2(unsigned long long& acc,
                                            unsigned long long a,
                                            unsigned long long b) {
    asm("fma.rn.f32x2 %0, %1, %2, %0;" : "+l"(acc) : "l"(a), "l"(b));
}

// y (or y +=) relu(x) @ W + b ; W is [32][32] row-major in SMEM (128B-aligned rows)
template <bool ADD>
static __device__ __forceinline__ void gemv32(const float* __restrict__ Wsm,
                                              const float* __restrict__ bsm,
                                              const float x[DD], float y[DD]) {
    unsigned long long acc[16];
#pragma unroll
    for (int k = 0; k < 16; k++) acc[k] = pack2(bsm[2 * k], bsm[2 * k + 1]);
#pragma unroll
    for (int i = 0; i < DD; i++) {
        float xi = fmaxf(x[i], 0.0f);
        unsigned long long xx = pack2(xi, xi);
        const ulonglong2* wr = reinterpret_cast<const ulonglong2*>(Wsm + i * DD);
#pragma unroll
        for (int k = 0; k < 8; k++) {
            ulonglong2 wv = wr[k];          // LDS.128, broadcast across warp
            fma2(acc[2 * k],     xx, wv.x); // outputs 4k .. 4k+1
            fma2(acc[2 * k + 1], xx, wv.y); // outputs 4k+2 .. 4k+3
        }
    }
#pragma unroll
    for (int k = 0; k < 16; k++) {
        float a, bv;
        unpack2(acc[k], a, bv);
        if (ADD) { y[2 * k] += a; y[2 * k + 1] += bv; }
        else     { y[2 * k]  = a; y[2 * k + 1]  = bv; }
    }
}

extern __shared__ float smem[];

__global__ void __launch_bounds__(THREADS, 2)
decoder_kernel(const float* __restrict__ p,
               const float* __restrict__ c,
               const float* __restrict__ Cm,
               const float* __restrict__ Wp, const float* __restrict__ bp,
               const float* __restrict__ W0, const float* __restrict__ b0,
               const float* __restrict__ W1, const float* __restrict__ b1,
               const float* __restrict__ Wo, const float* __restrict__ bo,
               float* __restrict__ out) {
    const int tid   = threadIdx.x;
    const int blk   = blockIdx.x;
    const int b     = blk >> 4;       // 16 tiles of 256 points per batch (T=4096)
    const int gbase = blk * TILE;

    // ---- stage weights + per-block data into SMEM ----
    for (int i = tid; i < 5120; i += THREADS) { smem[OFF_W0 + i] = W0[i]; smem[OFF_W1 + i] = W1[i]; }
    for (int i = tid; i < 160;  i += THREADS) { smem[OFF_B0 + i] = b0[i]; smem[OFF_B1 + i] = b1[i]; }
    if (tid < 96)  smem[OFF_WP + tid] = Wp[tid];
    if (tid < 32)  { smem[OFF_BP + tid] = bp[tid]; smem[OFF_WO + tid] = Wo[tid]; }
    if (tid == 0)  smem[OFF_BO] = bo[0];
    for (int i = tid; i < 48; i += THREADS)       smem[OFF_C + i] = Cm[b * 48 + i];
    for (int i = tid; i < TILE * 3; i += THREADS) smem[OFF_P + i] = p[gbase * 3 + i];
    __syncthreads();

    // ---- phase A: bilinear gather, warp per point, lane = channel ----
    {
        const int w = tid >> 5, lane = tid & 31;
        const float* __restrict__ cB = c + (size_t)b * NVIEW * HW * HW * DD;
        // Pre-scale each view's projection rows by 1/(C[3][0]+0.05) once.
        float m[NVIEW][6];
#pragma unroll
        for (int l = 0; l < NVIEW; l++) {
            const float* Cl = smem + OFF_C + l * 12;
            const float inv = 1.0f / (Cl[9] + 0.05f);
#pragma unroll
            for (int q = 0; q < 6; q++) m[l][q] = Cl[q] * inv;
        }
        for (int k = w * 32; k < w * 32 + 32; ++k) {
            const float* pp = smem + OFF_P + k * 3;
            const float px = pp[0] * (1.0f / 0.55f);
            const float py = pp[1] * (1.0f / 0.55f);
            const float pz = pp[2] * (1.0f / 0.55f);
            float cf = 0.0f;
#pragma unroll
            for (int l = 0; l < NVIEW; l++) {
                float xg = m[l][0] * px + m[l][1] * py + m[l][2] * pz;
                float yg = m[l][3] * px + m[l][4] * py + m[l][5] * pz;
                xg = (xg + 1.0f) * 63.5f;
                yg = (yg + 1.0f) * 63.5f;
                xg = (xg >= 127.0f) ? 126.9f : xg;  xg = (xg < 0.0f) ? 0.0f : xg;
                yg = (yg >= 127.0f) ? 126.9f : yg;  yg = (yg < 0.0f) ? 0.0f : yg;
                // round-half-to-even matches jnp.round
                const float xl  = rintf(xg - 0.5f), xr  = rintf(xg + 0.5f);
                const float ylo = rintf(yg - 0.5f), yhi = rintf(yg + 0.5f);
                const float dx = xr - xg, dy = yhi - yg;
                const int il = (int)xl, ir = (int)xr, jl = (int)ylo, jh = (int)yhi;
                const float* vb = cB + (size_t)l * HW * HW * DD;
                // each corner row is exactly one 128B line; lane-indexed load is fully coalesced
                const float f11 = vb[(il * HW + jl) * DD + lane];
                const float f12 = vb[(ir * HW + jl) * DD + lane];
                const float f21 = vb[(il * HW + jh) * DD + lane];
                const float f22 = vb[(ir * HW + jh) * DD + lane];
                cf += f11 * (dx * dy) + f12 * ((1.0f - dx) * dy)
                    + f21 * (dx * (1.0f - dy)) + f22 * ((1.0f - dx) * (1.0f - dy));
            }
            smem[OFF_CF + k * 33 + lane] = cf;   // stride 33 -> conflict-free both ways
        }
    }
    __syncthreads();

    // ---- phase B: MLP, thread per point ----
    {
        const float* __restrict__ cfr = smem + OFF_CF + tid * 33;
        const float pa = smem[OFF_P + tid * 3];
        const float pb = smem[OFF_P + tid * 3 + 1];
        const float pc = smem[OFF_P + tid * 3 + 2];
        float net[DD], tmp[DD];
#pragma unroll
        for (int j = 0; j < DD; j++) {
            float v = smem[OFF_BP + j];
            v = fmaf(pa, smem[OFF_WP + j],       v);
            v = fmaf(pb, smem[OFF_WP + 32 + j],  v);
            v = fmaf(pc, smem[OFF_WP + 64 + j],  v);
            net[j] = v + cfr[j];                 // cf added before block 0
        }
#pragma unroll 1
        for (int rb = 0; rb < 5; ++rb) {
            if (rb) {
#pragma unroll
                for (int j = 0; j < DD; j++) net[j] += cfr[j];  // cf re-added before blocks 1..4
            }
            gemv32<false>(smem + OFF_W0 + rb * 1024, smem + OFF_B0 + rb * 32, net, tmp);
            gemv32<true >(smem + OFF_W1 + rb * 1024, smem + OFF_B1 + rb * 32, tmp, net);
        }
        float s = smem[OFF_BO];
#pragma unroll
        for (int j = 0; j < DD; j++) s = fmaf(fmaxf(net[j], 0.0f), smem[OFF_WO + j], s);
        out[gbase + tid] = s;
    }
}

extern "C" void kernel_launch(void* const* d_in, const int* in_sizes, int n_in,
                              void* d_out, int out_size) {
    (void)in_sizes; (void)n_in; (void)out_size;
    const float* p  = (const float*)d_in[0];
    // d_in[1] is z — unused by the reference network
    const float* c  = (const float*)d_in[2];
    const float* Cm = (const float*)d_in[3];
    const float* Wp = (const float*)d_in[4];
    const float* bp = (const float*)d_in[5];
    const float* W0 = (const float*)d_in[6];
    const float* b0 = (const float*)d_in[7];
    const float* W1 = (const float*)d_in[8];
    const float* b1 = (const float*)d_in[9];
    const float* Wo = (const float*)d_in[10];
    const float* bo = (const float*)d_in[11];
    float* out = (float*)d_out;

    cudaFuncSetAttribute(decoder_kernel,
                         cudaFuncAttributeMaxDynamicSharedMemorySize, SMEM_BYTES);
    decoder_kernel<<<NBLK, THREADS, SMEM_BYTES>>>(p, c, Cm, Wp, bp, W0, b0, W1, b1,
                                                  Wo, bo, out);
}

// round 8
// speedup vs baseline: 1.1411x; 1.1411x over previous
#include <cuda_runtime.h>
#include <cstdint>
#include <cstddef>

// DecoderCBatchNorm fused kernel.  B=16, T=4096, L=4, H=W=128, D=32.
// Phase A: warp-cooperative bilinear gather (lane = channel), 2-point unroll.
// Phase B: 2 points per thread; weight LDS.128 shared across both points.

#define THREADS 128
#define TILE    256
#define NBLK    256        // 65536 points / 256
#define NVIEW   4
#define HW      128
#define DD      32

// shared-memory float offsets
#define OFF_W0   0          // 5 x 32 x 32
#define OFF_W1   5120
#define OFF_B0   10240      // 5 x 32
#define OFF_B1   10400
#define OFF_WP   10560      // 3 x 32
#define OFF_BP   10656      // 32
#define OFF_WO   10688      // 32
#define OFF_BO   10720      // 1 (+pad to 4)
#define OFF_C    10724      // 4 x 12
#define OFF_P    10772      // 256 x 3
#define OFF_CF   11540      // 256 x 32, XOR-swizzled
#define SMEM_FLOATS 19732
#define SMEM_BYTES  (SMEM_FLOATS * 4)

static __device__ __forceinline__ unsigned long long pack2(float a, float b) {
    unsigned long long r;
    asm("mov.b64 %0, {%1, %2};" : "=l"(r) : "f"(a), "f"(b));
    return r;
}
static __device__ __forceinline__ void unpack2(unsigned long long v, float& a, float& b) {
    asm("mov.b64 {%0, %1}, %2;" : "=f"(a), "=f"(b) : "l"(v));
}
static __device__ __forceinline__ void fma2(unsigned long long& acc,
                                            unsigned long long a,
                                            unsigned long long b) {
    asm("fma.rn.f32x2 %0, %1, %2, %0;" : "+l"(acc) : "l"(a), "l"(b));
}

// Dual-point GEMV: {yA,yB} = relu({xA,xB}) @ W + b (+ carry if CARRY).
// One weight-row LDS.128 feeds 4 fma2 (2 per point).
template <bool CARRY>
static __device__ __forceinline__ void gemv32x2(const float* __restrict__ Wsm,
                                                const float* __restrict__ bsm,
                                                const float xA[DD], const float xB[DD],
                                                const float cA[DD], const float cB2[DD],
                                                float yA[DD], float yB[DD]) {
    unsigned long long accA[16], accB[16];
#pragma unroll
    for (int k = 0; k < 16; k++) {
        const float b0 = bsm[2 * k], b1 = bsm[2 * k + 1];
        if (CARRY) {
            accA[k] = pack2(b0 + cA[2 * k],  b1 + cA[2 * k + 1]);
            accB[k] = pack2(b0 + cB2[2 * k], b1 + cB2[2 * k + 1]);
        } else {
            accA[k] = pack2(b0, b1);
            accB[k] = pack2(b0, b1);
        }
    }
#pragma unroll
    for (int i = 0; i < DD; i++) {
        const float xa = fmaxf(xA[i], 0.0f);
        const float xb = fmaxf(xB[i], 0.0f);
        const unsigned long long va = pack2(xa, xa);
        const unsigned long long vb = pack2(xb, xb);
        const ulonglong2* wr = reinterpret_cast<const ulonglong2*>(Wsm + i * DD);
#pragma unroll
        for (int k = 0; k < 8; k++) {
            const ulonglong2 wv = wr[k];         // LDS.128 broadcast, shared by both points
            fma2(accA[2 * k],     va, wv.x);
            fma2(accB[2 * k],     vb, wv.x);
            fma2(accA[2 * k + 1], va, wv.y);
            fma2(accB[2 * k + 1], vb, wv.y);
        }
    }
#pragma unroll
    for (int k = 0; k < 16; k++) {
        unpack2(accA[k], yA[2 * k], yA[2 * k + 1]);
        unpack2(accB[k], yB[2 * k], yB[2 * k + 1]);
    }
}

extern __shared__ float smem[];

__global__ void __launch_bounds__(THREADS, 2)
decoder_kernel(const float* __restrict__ p,
               const float* __restrict__ c,
               const float* __restrict__ Cm,
               const float* __restrict__ Wp, const float* __restrict__ bp,
               const float* __restrict__ W0, const float* __restrict__ b0,
               const float* __restrict__ W1, const float* __restrict__ b1,
               const float* __restrict__ Wo, const float* __restrict__ bo,
               float* __restrict__ out) {
    const int tid   = threadIdx.x;
    const int blk   = blockIdx.x;
    const int b     = blk >> 4;       // 16 tiles of 256 points per batch
    const int gbase = blk * TILE;

    // ---- stage weights + per-block data into SMEM ----
    for (int i = tid; i < 5120; i += THREADS) { smem[OFF_W0 + i] = W0[i]; smem[OFF_W1 + i] = W1[i]; }
    for (int i = tid; i < 160;  i += THREADS) { smem[OFF_B0 + i] = b0[i]; smem[OFF_B1 + i] = b1[i]; }
    if (tid < 96)  smem[OFF_WP + tid] = Wp[tid];
    if (tid < 32)  { smem[OFF_BP + tid] = bp[tid]; smem[OFF_WO + tid] = Wo[tid]; }
    if (tid == 0)  smem[OFF_BO] = bo[0];
    for (int i = tid; i < 48; i += THREADS)       smem[OFF_C + i] = Cm[b * 48 + i];
    for (int i = tid; i < TILE * 3; i += THREADS) smem[OFF_P + i] = p[gbase * 3 + i];
    __syncthreads();

    // ---- phase A: bilinear gather, warp per 64 points, 2-point unroll ----
    {
        const int w = tid >> 5, lane = tid & 31;
        const float* __restrict__ cB = c + (size_t)b * NVIEW * HW * HW * DD;
        float m[NVIEW][6];
#pragma unroll
        for (int l = 0; l < NVIEW; l++) {
            const float* Cl = smem + OFF_C + l * 12;
            const float inv = 1.0f / (Cl[9] + 0.05f);
#pragma unroll
            for (int q = 0; q < 6; q++) m[l][q] = Cl[q] * inv;
        }
        for (int k0 = w * 64; k0 < w * 64 + 64; k0 += 2) {
            // compute all 8 (point,view) corner sets first, then issue all 32 loads
            int   base_l[2][NVIEW], base_r[2][NVIEW], jlo[2][NVIEW], jhi[2][NVIEW];
            float dxv[2][NVIEW], dyv[2][NVIEW];
#pragma unroll
            for (int u = 0; u < 2; u++) {
                const float* pp = smem + OFF_P + (k0 + u) * 3;
                const float px = pp[0] * (1.0f / 0.55f);
                const float py = pp[1] * (1.0f / 0.55f);
                const float pz = pp[2] * (1.0f / 0.55f);
#pragma unroll
                for (int l = 0; l < NVIEW; l++) {
                    float xg = m[l][0] * px + m[l][1] * py + m[l][2] * pz;
                    float yg = m[l][3] * px + m[l][4] * py + m[l][5] * pz;
                    xg = (xg + 1.0f) * 63.5f;
                    yg = (yg + 1.0f) * 63.5f;
                    xg = (xg >= 127.0f) ? 126.9f : xg;  xg = (xg < 0.0f) ? 0.0f : xg;
                    yg = (yg >= 127.0f) ? 126.9f : yg;  yg = (yg < 0.0f) ? 0.0f : yg;
                    // round-half-to-even matches jnp.round
                    const float xl  = rintf(xg - 0.5f), xr  = rintf(xg + 0.5f);
                    const float ylo = rintf(yg - 0.5f), yhi = rintf(yg + 0.5f);
                    dxv[u][l] = xr - xg;  dyv[u][l] = yhi - yg;
                    const int il = (int)xl, ir = (int)xr;
                    jlo[u][l] = (int)ylo; jhi[u][l] = (int)yhi;
                    base_l[u][l] = (l * HW * HW + il * HW) * DD;
                    base_r[u][l] = (l * HW * HW + ir * HW) * DD;
                }
            }
            float f11[2][NVIEW], f12[2][NVIEW], f21[2][NVIEW], f22[2][NVIEW];
#pragma unroll
            for (int u = 0; u < 2; u++)
#pragma unroll
                for (int l = 0; l < NVIEW; l++) {
                    // each corner row is exactly one 128B line; lane-indexed, coalesced
                    f11[u][l] = cB[base_l[u][l] + jlo[u][l] * DD + lane];
                    f12[u][l] = cB[base_r[u][l] + jlo[u][l] * DD + lane];
                    f21[u][l] = cB[base_l[u][l] + jhi[u][l] * DD + lane];
                    f22[u][l] = cB[base_r[u][l] + jhi[u][l] * DD + lane];
                }
#pragma unroll
            for (int u = 0; u < 2; u++) {
                float cf = 0.0f;
#pragma unroll
                for (int l = 0; l < NVIEW; l++) {
                    const float dx = dxv[u][l], dy = dyv[u][l];
                    cf += f11[u][l] * (dx * dy) + f12[u][l] * ((1.0f - dx) * dy)
                        + f21[u][l] * (dx * (1.0f - dy)) + f22[u][l] * ((1.0f - dx) * (1.0f - dy));
                }
                const int k = k0 + u;
                smem[OFF_CF + k * DD + (lane ^ (k & 31))] = cf;  // XOR swizzle, conflict-free
            }
        }
    }
    __syncthreads();

    // ---- phase B: MLP, 2 points per thread (t and t+128) ----
    {
        const int pA = tid, pB = tid + 128;
        float cfA[DD], cfB[DD];
#pragma unroll
        for (int j = 0; j < DD; j++) {
            cfA[j] = smem[OFF_CF + pA * DD + (j ^ (pA & 31))];
            cfB[j] = smem[OFF_CF + pB * DD + (j ^ (pB & 31))];
        }
        const float paA = smem[OFF_P + pA * 3],     paB = smem[OFF_P + pB * 3];
        const float pbA = smem[OFF_P + pA * 3 + 1], pbB = smem[OFF_P + pB * 3 + 1];
        const float pcA = smem[OFF_P + pA * 3 + 2], pcB = smem[OFF_P + pB * 3 + 2];

        float netA[DD], netB[DD], hA[DD], hB[DD];
#pragma unroll
        for (int j = 0; j < DD; j++) {
            const float w0j = smem[OFF_WP + j];
            const float w1j = smem[OFF_WP + 32 + j];
            const float w2j = smem[OFF_WP + 64 + j];
            const float bj  = smem[OFF_BP + j];
            netA[j] = fmaf(paA, w0j, fmaf(pbA, w1j, fmaf(pcA, w2j, bj))) + cfA[j];
            netB[j] = fmaf(paB, w0j, fmaf(pbB, w1j, fmaf(pcB, w2j, bj))) + cfB[j];
        }
#pragma unroll 1
        for (int rb = 0; rb < 5; ++rb) {
            if (rb) {
#pragma unroll
                for (int j = 0; j < DD; j++) { netA[j] += cfA[j]; netB[j] += cfB[j]; }
            }
            gemv32x2<false>(smem + OFF_W0 + rb * 1024, smem + OFF_B0 + rb * 32,
                            netA, netB, netA, netB, hA, hB);
            // carry-init: acc = b1 + net, so net dies before the main loop
            gemv32x2<true >(smem + OFF_W1 + rb * 1024, smem + OFF_B1 + rb * 32,
                            hA, hB, netA, netB, netA, netB);
        }
        float sA = smem[OFF_BO], sB = sA;
#pragma unroll
        for (int j = 0; j < DD; j++) {
            const float wj = smem[OFF_WO + j];
            sA = fmaf(fmaxf(netA[j], 0.0f), wj, sA);
            sB = fmaf(fmaxf(netB[j], 0.0f), wj, sB);
        }
        out[gbase + pA] = sA;
        out[gbase + pB] = sB;
    }
}

extern "C" void kernel_launch(void* const* d_in, const int* in_sizes, int n_in,
                              void* d_out, int out_size) {
    (void)in_sizes; (void)n_in; (void)out_size;
    const float* p  = (const float*)d_in[0];
    // d_in[1] is z — unused by the reference network
    const float* c  = (const float*)d_in[2];
    const float* Cm = (const float*)d_in[3];
    const float* Wp = (const float*)d_in[4];
    const float* bp = (const float*)d_in[5];
    const float* W0 = (const float*)d_in[6];
    const float* b0 = (const float*)d_in[7];
    const float* W1 = (const float*)d_in[8];
    const float* b1 = (const float*)d_in[9];
    const float* Wo = (const float*)d_in[10];
    const float* bo = (const float*)d_in[11];
    float* out = (float*)d_out;

    cudaFuncSetAttribute(decoder_kernel,
                         cudaFuncAttributeMaxDynamicSharedMemorySize, SMEM_BYTES);
    decoder_kernel<<<NBLK, THREADS, SMEM_BYTES>>>(p, c, Cm, Wp, bp, W0, b0, W1, b1,
                                                  Wo, bo, out);
}